// round 8
// baseline (speedup 1.0000x reference)
#include <cuda_runtime.h>
#include <cuda_fp16.h>
#include <math.h>
#include <stdint.h>

#define KNOTS   16
#define BOUNDV  5.0f
#define XDIM    6
#define CDIM    4
#define HID     128
#define SPLD    47
#define LOWERD  3
#define OUTD    141
#define NPAD    144
#define GROWS   64        // rows per group-tile
#define NTHREADS 512

#define AST   136   // A tile stride (halves)
#define W2ST  136
#define W3ST  152
#define PST   147   // P stride (floats)

// ---- smem byte offsets (two groups) ----
#define ABYTES   17408                 // 64*136*2 per group
#define OFF_AH   0                     // + g*ABYTES   (34816 total)
#define OFF_AL   34816                 // + g*ABYTES   (34816 total)
#define OFF_W2   69632                 // 34816 shared
#define OFF_W3   104448                // 38912 shared
#define OFF_P    143360                // + g*37632    (75264 total)
#define OFF_IN   218624                // + g*2048
#define OFF_LOW  222720                // + g*1024
#define OFF_W1   224768                // 3584
#define OFF_B1   228352                // 512
#define OFF_B2   228864                // 512
#define OFF_B3   229376                // 576
#define OFF_LD   229952                // + g*1024
#define SMEM_BYTES 232000

#define GBAR()  asm volatile("bar.sync %0, 256;" :: "r"(gbar) : "memory")

static __device__ __forceinline__ uint32_t smem_u32(const void* p) {
    uint32_t a;
    asm("{ .reg .u64 t; cvta.to.shared.u64 t, %1; cvt.u32.u64 %0, t; }" : "=r"(a) : "l"(p));
    return a;
}

static __device__ __forceinline__ void ldsm_x4(uint32_t a, uint32_t& r0, uint32_t& r1,
                                               uint32_t& r2, uint32_t& r3) {
    asm volatile("ldmatrix.sync.aligned.m8n8.x4.shared.b16 {%0,%1,%2,%3}, [%4];"
                 : "=r"(r0), "=r"(r1), "=r"(r2), "=r"(r3) : "r"(a));
}
static __device__ __forceinline__ void ldsm_x4t(uint32_t a, uint32_t& r0, uint32_t& r1,
                                                uint32_t& r2, uint32_t& r3) {
    asm volatile("ldmatrix.sync.aligned.m8n8.x4.trans.shared.b16 {%0,%1,%2,%3}, [%4];"
                 : "=r"(r0), "=r"(r1), "=r"(r2), "=r"(r3) : "r"(a));
}
static __device__ __forceinline__ void ldsm_x2t(uint32_t a, uint32_t& r0, uint32_t& r1) {
    asm volatile("ldmatrix.sync.aligned.m8n8.x2.trans.shared.b16 {%0,%1}, [%2];"
                 : "=r"(r0), "=r"(r1) : "r"(a));
}
static __device__ __forceinline__ void mma16816(float* c, const uint32_t* a,
                                                uint32_t b0, uint32_t b1) {
    asm volatile("mma.sync.aligned.m16n8k16.row.col.f32.f16.f16.f32 "
                 "{%0,%1,%2,%3}, {%4,%5,%6,%7}, {%8,%9}, {%0,%1,%2,%3};"
                 : "+f"(c[0]), "+f"(c[1]), "+f"(c[2]), "+f"(c[3])
                 : "r"(a[0]), "r"(a[1]), "r"(a[2]), "r"(a[3]), "r"(b0), "r"(b1));
}

// ---- FFMA-pipe exp (valid for x <= ~0; clamps hard underflow) ----
static __device__ __forceinline__ float fexp(float x) {
    float t = x * 1.4426950408889634f;
    t = fmaxf(t, -125.0f);
    float r = t + 12582912.0f;
    float fi = r - 12582912.0f;
    float f = t - fi;
    int i = (int)fi;
    float p = 1.5403530393e-4f;
    p = fmaf(p, f, 1.3333558146e-3f);
    p = fmaf(p, f, 9.6181291076e-3f);
    p = fmaf(p, f, 5.5504108664e-2f);
    p = fmaf(p, f, 2.4022650696e-1f);
    p = fmaf(p, f, 6.9314718056e-1f);
    p = fmaf(p, f, 1.0f);
    return __int_as_float(__float_as_int(p) + (i << 23));
}

// ---- FFMA-pipe natural log (u > 0, normal) ----
static __device__ __forceinline__ float flog(float u) {
    int ib = __float_as_int(u);
    int e = (ib - 0x3f3504f3) >> 23;
    float m = __int_as_float(ib - (e << 23));
    float f = m - 1.0f;
    float z = f * f;
    float P = 7.0376836292e-2f;
    P = fmaf(P, f, -1.1514610310e-1f);
    P = fmaf(P, f, 1.1676998740e-1f);
    P = fmaf(P, f, -1.2420140846e-1f);
    P = fmaf(P, f, 1.4249322787e-1f);
    P = fmaf(P, f, -1.6668057665e-1f);
    P = fmaf(P, f, 2.0000714765e-1f);
    P = fmaf(P, f, -2.4999993993e-1f);
    P = fmaf(P, f, 3.3333331174e-1f);
    float rr = fmaf(P * z, f, fmaf(-0.5f, z, f));
    return fmaf((float)e, 0.69314718055994531f, rr);
}

static __device__ __forceinline__ float softplus_f(float v) {
    return fmaxf(v, 0.0f) + flog(1.0f + fexp(-fabsf(v)));
}

__global__ __launch_bounds__(NTHREADS, 1)
void nsc_hmma_kernel(const float* __restrict__ x, const float* __restrict__ c,
                     const float* __restrict__ W1, const float* __restrict__ b1,
                     const float* __restrict__ W2, const float* __restrict__ b2,
                     const float* __restrict__ W3, const float* __restrict__ b3,
                     float* __restrict__ out, int B, int ntiles)
{
    extern __shared__ char smb[];
    const uint32_t sb = smem_u32(smb);

    __half* hW2 = (__half*)(smb + OFF_W2);
    __half* hW3 = (__half*)(smb + OFF_W3);
    float* sW1  = (float*)(smb + OFF_W1);
    float* sB1  = (float*)(smb + OFF_B1);
    float* sB2  = (float*)(smb + OFF_B2);
    float* sB3  = (float*)(smb + OFF_B3);

    const int tid = threadIdx.x;
    const int g   = tid >> 8;          // group 0/1
    const int gt  = tid & 255;         // tid within group
    const int gbar = 1 + g;
    const int warp = gt >> 5;          // 0..7 within group
    const int lane = tid & 31;
    const int wm = warp >> 1;          // 0..3 -> m0 = wm*16
    const int wn = warp & 1;
    const int m0 = wm * 16;
    const int lr = lane & 15;
    const int lc = (lane >> 4) * 8;
    const int grow = lane >> 2;
    const int gcol = (lane & 3) * 2;

    // group-local buffers
    __half* gAh = (__half*)(smb + OFF_AH + g * ABYTES);
    __half* gAl = (__half*)(smb + OFF_AL + g * ABYTES);
    const uint32_t sbAh = sb + OFF_AH + g * ABYTES;
    const uint32_t sbAl = sb + OFF_AL + g * ABYTES;
    float* gP   = (float*)(smb + OFF_P  + g * 37632);
    float* gIn  = (float*)(smb + OFF_IN + g * 2048);
    float* gLow = (float*)(smb + OFF_LOW + g * 1024);
    float* gLd  = (float*)(smb + OFF_LD + g * 1024);

    // ---- one-time weight staging (full CTA) ----
    for (int i = tid; i < HID * HID; i += NTHREADS) {
        int k = i >> 7, n = i & 127;
        hW2[k * W2ST + n] = __float2half_rn(W2[i]);
    }
    for (int i = tid; i < HID * NPAD; i += NTHREADS) {
        int k = i / NPAD, n = i - k * NPAD;
        hW3[k * W3ST + n] = __float2half_rn((n < OUTD) ? W3[k * OUTD + n] : 0.0f);
    }
    for (int i = tid; i < 7 * HID; i += NTHREADS) sW1[i] = W1[i];
    if (tid < HID) { sB1[tid] = b1[tid]; sB2[tid] = b2[tid]; }
    if (tid < NPAD) sB3[tid] = (tid < OUTD) ? b3[tid] : 0.0f;
    __syncthreads();   // last full-CTA sync; groups diverge after this

    for (long tile = (long)blockIdx.x * 2 + g; tile < ntiles;
         tile += (long)gridDim.x * 2) {
        const long base = tile * GROWS;
        const int nrows = (int)min((long)GROWS, (long)B - base);
        GBAR();   // previous iteration fully done with group buffers

        // ---- stage inputs ----
        for (int i = gt; i < GROWS * XDIM; i += 256) {
            int r = i / XDIM, cc = i - r * XDIM;
            float v = (r < nrows) ? x[(base + r) * XDIM + cc] : 0.0f;
            if (cc < LOWERD) gLow[r * 4 + cc] = v;
            else             gIn[r * 8 + (cc - LOWERD)] = v;
        }
        for (int i = gt; i < GROWS * CDIM; i += 256) {
            int r = i >> 2, cc = i & 3;
            gIn[r * 8 + 3 + cc] = (r < nrows) ? c[(base + r) * CDIM + cc] : 0.0f;
        }
        GBAR();

        // ---- layer 1 (fp32) -> split fp16 A ----
        for (int t = gt; t < GROWS * 64; t += 256) {
            int r = t >> 6, np = (t & 63) << 1;
            float a0 = sB1[np], a1 = sB1[np + 1];
            const float* inr = &gIn[r * 8];
            #pragma unroll
            for (int k = 0; k < 7; k++) {
                float iv = inr[k];
                a0 = fmaf(iv, sW1[k * HID + np], a0);
                a1 = fmaf(iv, sW1[k * HID + np + 1], a1);
            }
            a0 = fmaxf(a0, 0.0f); a1 = fmaxf(a1, 0.0f);
            __half h0 = __float2half_rn(a0), h1v = __float2half_rn(a1);
            __half l0 = __float2half_rn(a0 - __half2float(h0));
            __half l1 = __float2half_rn(a1 - __half2float(h1v));
            *(__half2*)&gAh[r * AST + np] = __halves2half2(h0, h1v);
            *(__half2*)&gAl[r * AST + np] = __halves2half2(l0, l1);
        }
        GBAR();

        // ---- GEMM2: 64x128x128 per group, split-A, warp tile 16x64 ----
        float acc[8][4];
        {
            #pragma unroll
            for (int nt = 0; nt < 8; nt++)
                #pragma unroll
                for (int q = 0; q < 4; q++) acc[nt][q] = 0.0f;
            const int n0 = wn * 64;
            #pragma unroll
            for (int kk = 0; kk < 8; kk++) {
                const int kb = kk * 16;
                uint32_t ah[4], al[4], bb[4][4];
                uint32_t aoff = (uint32_t)(((m0 + lr) * AST + kb + lc) * 2);
                ldsm_x4(sbAh + aoff, ah[0], ah[1], ah[2], ah[3]);
                ldsm_x4(sbAl + aoff, al[0], al[1], al[2], al[3]);
                #pragma unroll
                for (int np = 0; np < 4; np++) {
                    uint32_t boff = (uint32_t)(((kb + lr) * W2ST + n0 + np * 16 + lc) * 2);
                    ldsm_x4t(sb + OFF_W2 + boff, bb[np][0], bb[np][1], bb[np][2], bb[np][3]);
                }
                #pragma unroll
                for (int np = 0; np < 4; np++)
                    #pragma unroll
                    for (int j = 0; j < 2; j++) {
                        float* cc4 = acc[np * 2 + j];
                        mma16816(cc4, ah, bb[np][2 * j], bb[np][2 * j + 1]);
                        mma16816(cc4, al, bb[np][2 * j], bb[np][2 * j + 1]);
                    }
            }
        }
        GBAR();

        // ---- h2 = relu(D + b2) -> split fp16 A (overwrite) ----
        {
            const int n0 = wn * 64;
            #pragma unroll
            for (int nt = 0; nt < 8; nt++) {
                int col = n0 + nt * 8 + gcol;
                float bb0 = sB2[col], bb1 = sB2[col + 1];
                #pragma unroll
                for (int h = 0; h < 2; h++) {
                    int r = m0 + grow + h * 8;
                    float v0 = fmaxf(acc[nt][2 * h]     + bb0, 0.0f);
                    float v1 = fmaxf(acc[nt][2 * h + 1] + bb1, 0.0f);
                    __half h0 = __float2half_rn(v0), h1v = __float2half_rn(v1);
                    __half l0 = __float2half_rn(v0 - __half2float(h0));
                    __half l1 = __float2half_rn(v1 - __half2float(h1v));
                    *(__half2*)&gAh[r * AST + col] = __halves2half2(h0, h1v);
                    *(__half2*)&gAl[r * AST + col] = __halves2half2(l0, l1);
                }
            }
        }
        GBAR();

        // ---- GEMM3: 64x144x128 per group, split-A, warp tile 16x72 ----
        {
            float a3[9][4];
            #pragma unroll
            for (int nt = 0; nt < 9; nt++)
                #pragma unroll
                for (int q = 0; q < 4; q++) a3[nt][q] = 0.0f;
            const int n0 = wn * 72;
            #pragma unroll
            for (int kk = 0; kk < 8; kk++) {
                const int kb = kk * 16;
                uint32_t ah[4], al[4], bb[4][4], be[2];
                uint32_t aoff = (uint32_t)(((m0 + lr) * AST + kb + lc) * 2);
                ldsm_x4(sbAh + aoff, ah[0], ah[1], ah[2], ah[3]);
                ldsm_x4(sbAl + aoff, al[0], al[1], al[2], al[3]);
                #pragma unroll
                for (int np = 0; np < 4; np++) {
                    uint32_t boff = (uint32_t)(((kb + lr) * W3ST + n0 + np * 16 + lc) * 2);
                    ldsm_x4t(sb + OFF_W3 + boff, bb[np][0], bb[np][1], bb[np][2], bb[np][3]);
                }
                {
                    uint32_t boff = (uint32_t)(((kb + lr) * W3ST + n0 + 64) * 2);
                    ldsm_x2t(sb + OFF_W3 + boff, be[0], be[1]);
                }
                #pragma unroll
                for (int np = 0; np < 4; np++)
                    #pragma unroll
                    for (int j = 0; j < 2; j++) {
                        float* cc4 = a3[np * 2 + j];
                        mma16816(cc4, ah, bb[np][2 * j], bb[np][2 * j + 1]);
                        mma16816(cc4, al, bb[np][2 * j], bb[np][2 * j + 1]);
                    }
                mma16816(a3[8], ah, be[0], be[1]);
                mma16816(a3[8], al, be[0], be[1]);
            }
            #pragma unroll
            for (int nt = 0; nt < 9; nt++) {
                int col = n0 + nt * 8 + gcol;
                float bb0 = sB3[col], bb1 = sB3[col + 1];
                #pragma unroll
                for (int h = 0; h < 2; h++) {
                    int r = m0 + grow + h * 8;
                    gP[r * PST + col]     = a3[nt][2 * h]     + bb0;
                    gP[r * PST + col + 1] = a3[nt][2 * h + 1] + bb1;
                }
            }
        }
        GBAR();

        // ---- spline epilogue (192 items over 256 threads) ----
        if (gt < GROWS * LOWERD) {
            const int item = gt;
            const int r = item / 3;
            const int d = item - r * 3;
            const float* p = &gP[r * PST + d * SPLD];
            const float xv = gLow[r * 4 + d];
            const bool oob = (xv <= -BOUNDV) || (xv >= BOUNDV);
            const float xm = oob ? -BOUNDV : xv;

            float mW = -1e30f;
            #pragma unroll
            for (int i = 0; i < KNOTS; i++) mW = fmaxf(mW, p[i]);
            float ew[KNOTS], S = 0.0f;
            #pragma unroll
            for (int i = 0; i < KNOTS; i++) { ew[i] = fexp(p[i] - mW); S += ew[i]; }
            const float invS = __fdividef(2.0f * BOUNDV, S);

            int idx = 0; float cumex = 0.0f, wsel = ew[0];
            bool found = false; float cum = 0.0f;
            #pragma unroll
            for (int i = 0; i < KNOTS; i++) {
                float cn = cum + ew[i];
                bool take = (!found) && (xm < fmaf(cn, invS, -BOUNDV));
                if (take) { found = true; idx = i; cumex = cum; wsel = ew[i]; }
                cum = cn;
            }
            if (!found) { idx = KNOTS - 1; cumex = cum - ew[KNOTS - 1]; wsel = ew[KNOTS - 1]; }

            const float xk_b = fmaf(cumex, invS, -BOUNDV);
            const float wk   = wsel * invS;

            float mH = -1e30f;
            #pragma unroll
            for (int i = 0; i < KNOTS; i++) mH = fmaxf(mH, p[KNOTS + i]);
            float SH = 0.0f, cumh = 0.0f, hsel = 0.0f;
            #pragma unroll
            for (int i = 0; i < KNOTS; i++) {
                float e = fexp(p[KNOTS + i] - mH);
                SH += e;
                if (i < idx)  cumh += e;
                if (i == idx) hsel = e;
            }
            const float invSH = __fdividef(2.0f * BOUNDV, SH);
            const float yk_b = fmaf(cumh, invSH, -BOUNDV);
            const float hk   = hsel * invSH;

            float d0 = 1.0f, d1 = 1.0f;
            if (idx > 0)         d0 = softplus_f(p[2 * KNOTS + idx - 1]);
            if (idx < KNOTS - 1) d1 = softplus_f(p[2 * KNOTS + idx]);

            const float rwk = __fdividef(1.0f, wk);
            const float sk = hk * rwk;
            float relx = fminf(fmaxf((xm - xk_b) * rwk, 0.0f), 1.0f);
            const float omr = 1.0f - relx;
            const float r1 = relx * omr;
            const float den = sk + (d1 + d0 - 2.0f * sk) * r1;
            const float rden = __fdividef(1.0f, den);
            const float num = hk * (sk * relx * relx + d0 * r1);
            float y = yk_b + num * rden;
            const float arg = d1 * relx * relx + 2.0f * sk * r1 + d0 * omr * omr;
            float ld = flog(sk * sk * arg * rden * rden);
            if (oob) { y = xv; ld = 0.0f; }

            gLd[r * 4 + d] = ld;
            if (r < nrows) {
                out[(base + r) * XDIM + d] = y;
                out[(base + r) * XDIM + LOWERD + d] = gIn[r * 8 + d];
            }
        }
        GBAR();
        if (gt < GROWS && gt < nrows)
            out[(long)B * XDIM + base + gt] =
                gLd[gt * 4] + gLd[gt * 4 + 1] + gLd[gt * 4 + 2];
    }
}

extern "C" void kernel_launch(void* const* d_in, const int* in_sizes, int n_in,
                              void* d_out, int out_size)
{
    const float* x  = (const float*)d_in[0];
    const float* c  = (const float*)d_in[1];
    const float* W1 = (const float*)d_in[2];
    const float* b1 = (const float*)d_in[3];
    const float* W2 = (const float*)d_in[4];
    const float* b2 = (const float*)d_in[5];
    const float* W3 = (const float*)d_in[6];
    const float* b3 = (const float*)d_in[7];
    (void)n_in; (void)out_size;

    const int B = in_sizes[0] / XDIM;
    const int ntiles = (B + GROWS - 1) / GROWS;
    float* out = (float*)d_out;

    int sms = 148;
    cudaDeviceGetAttribute(&sms, cudaDevAttrMultiProcessorCount, 0);
    int need = (ntiles + 1) / 2;
    int grid = sms < need ? sms : need;

    cudaFuncSetAttribute(nsc_hmma_kernel, cudaFuncAttributeMaxDynamicSharedMemorySize,
                         SMEM_BYTES);
    nsc_hmma_kernel<<<grid, NTHREADS, SMEM_BYTES>>>(x, c, W1, b1, W2, b2, W3, b3,
                                                    out, B, ntiles);
}

// round 9
// speedup vs baseline: 1.1427x; 1.1427x over previous
#include <cuda_runtime.h>
#include <cuda_fp16.h>
#include <math.h>
#include <stdint.h>

#define KNOTS   16
#define BOUNDV  5.0f
#define XDIM    6
#define CDIM    4
#define HID     128
#define SPLD    47
#define LOWERD  3
#define OUTD    141
#define NPAD    144
#define MROWS   128
#define NTHREADS 512

#define AST   136   // A tile stride (halves)
#define W2ST  136
#define W3ST  152
#define PST   147   // P stride (floats)

// ---- smem byte offsets ----
#define OFF_AH   0                     // 34816  Ah fp16 [128][136]
#define OFF_AL   34816                 // 34816  Al fp16 [128][136]
#define OFF_W2   69632                 // 34816  W2 fp16 [k=128][n pad 136]
#define OFF_W3   104448                // 38912  W3 fp16 [k=128][n pad 152]
#define OFF_P    143360                // 75264  P fp32 [128][147]
#define OFF_IN   218624                // 4096
#define OFF_LOW  222720                // 2048
#define OFF_W1   224768                // 3584
#define OFF_B1   228352                // 512
#define OFF_B2   228864                // 512
#define OFF_B3   229376                // 576
#define OFF_LD   229952                // 2048
#define SMEM_BYTES 232000

static __device__ __forceinline__ uint32_t smem_u32(const void* p) {
    uint32_t a;
    asm("{ .reg .u64 t; cvta.to.shared.u64 t, %1; cvt.u32.u64 %0, t; }" : "=r"(a) : "l"(p));
    return a;
}

static __device__ __forceinline__ void ldsm_x4(uint32_t a, uint32_t& r0, uint32_t& r1,
                                               uint32_t& r2, uint32_t& r3) {
    asm volatile("ldmatrix.sync.aligned.m8n8.x4.shared.b16 {%0,%1,%2,%3}, [%4];"
                 : "=r"(r0), "=r"(r1), "=r"(r2), "=r"(r3) : "r"(a));
}
static __device__ __forceinline__ void ldsm_x4t(uint32_t a, uint32_t& r0, uint32_t& r1,
                                                uint32_t& r2, uint32_t& r3) {
    asm volatile("ldmatrix.sync.aligned.m8n8.x4.trans.shared.b16 {%0,%1,%2,%3}, [%4];"
                 : "=r"(r0), "=r"(r1), "=r"(r2), "=r"(r3) : "r"(a));
}
static __device__ __forceinline__ void ldsm_x2t(uint32_t a, uint32_t& r0, uint32_t& r1) {
    asm volatile("ldmatrix.sync.aligned.m8n8.x2.trans.shared.b16 {%0,%1}, [%2];"
                 : "=r"(r0), "=r"(r1) : "r"(a));
}
static __device__ __forceinline__ void mma16816(float* c, const uint32_t* a,
                                                uint32_t b0, uint32_t b1) {
    asm volatile("mma.sync.aligned.m16n8k16.row.col.f32.f16.f16.f32 "
                 "{%0,%1,%2,%3}, {%4,%5,%6,%7}, {%8,%9}, {%0,%1,%2,%3};"
                 : "+f"(c[0]), "+f"(c[1]), "+f"(c[2]), "+f"(c[3])
                 : "r"(a[0]), "r"(a[1]), "r"(a[2]), "r"(a[3]), "r"(b0), "r"(b1));
}

// ---- FFMA-pipe exp (valid for x <= ~0; clamps hard underflow) ----
static __device__ __forceinline__ float fexp(float x) {
    float t = x * 1.4426950408889634f;
    t = fmaxf(t, -125.0f);
    float r = t + 12582912.0f;
    float fi = r - 12582912.0f;
    float f = t - fi;
    int i = (int)fi;
    float p = 1.5403530393e-4f;
    p = fmaf(p, f, 1.3333558146e-3f);
    p = fmaf(p, f, 9.6181291076e-3f);
    p = fmaf(p, f, 5.5504108664e-2f);
    p = fmaf(p, f, 2.4022650696e-1f);
    p = fmaf(p, f, 6.9314718056e-1f);
    p = fmaf(p, f, 1.0f);
    return __int_as_float(__float_as_int(p) + (i << 23));
}

// ---- FFMA-pipe natural log (u > 0, normal) ----
static __device__ __forceinline__ float flog(float u) {
    int ib = __float_as_int(u);
    int e = (ib - 0x3f3504f3) >> 23;
    float m = __int_as_float(ib - (e << 23));
    float f = m - 1.0f;
    float z = f * f;
    float P = 7.0376836292e-2f;
    P = fmaf(P, f, -1.1514610310e-1f);
    P = fmaf(P, f, 1.1676998740e-1f);
    P = fmaf(P, f, -1.2420140846e-1f);
    P = fmaf(P, f, 1.4249322787e-1f);
    P = fmaf(P, f, -1.6668057665e-1f);
    P = fmaf(P, f, 2.0000714765e-1f);
    P = fmaf(P, f, -2.4999993993e-1f);
    P = fmaf(P, f, 3.3333331174e-1f);
    float rr = fmaf(P * z, f, fmaf(-0.5f, z, f));
    return fmaf((float)e, 0.69314718055994531f, rr);
}

static __device__ __forceinline__ float softplus_f(float v) {
    return fmaxf(v, 0.0f) + flog(1.0f + fexp(-fabsf(v)));
}

__global__ __launch_bounds__(NTHREADS, 1)
void nsc_hmma_kernel(const float* __restrict__ x, const float* __restrict__ c,
                     const float* __restrict__ W1, const float* __restrict__ b1,
                     const float* __restrict__ W2, const float* __restrict__ b2,
                     const float* __restrict__ W3, const float* __restrict__ b3,
                     float* __restrict__ out, int B, int ntiles)
{
    extern __shared__ char smb[];
    const uint32_t sb = smem_u32(smb);

    __half* hAh = (__half*)(smb + OFF_AH);
    __half* hAl = (__half*)(smb + OFF_AL);
    __half* hW2 = (__half*)(smb + OFF_W2);
    __half* hW3 = (__half*)(smb + OFF_W3);
    float* sP   = (float*)(smb + OFF_P);
    float* sIn  = (float*)(smb + OFF_IN);
    float* sLow = (float*)(smb + OFF_LOW);
    float* sW1  = (float*)(smb + OFF_W1);
    float* sB1  = (float*)(smb + OFF_B1);
    float* sB2  = (float*)(smb + OFF_B2);
    float* sB3  = (float*)(smb + OFF_B3);
    float* sLd  = (float*)(smb + OFF_LD);

    const int tid = threadIdx.x;
    const int warp = tid >> 5;
    const int lane = tid & 31;
    const int wm = warp >> 1;          // 0..7  -> m0 = wm*16
    const int wn = warp & 1;           // 0..1
    const int m0 = wm * 16;
    const int lr = lane & 15;
    const int lc = (lane >> 4) * 8;
    const int grow = lane >> 2;
    const int gcol = (lane & 3) * 2;

    // ---- one-time weight staging (per CTA) ----
    for (int i = tid; i < HID * HID; i += NTHREADS) {
        int k = i >> 7, n = i & 127;
        hW2[k * W2ST + n] = __float2half_rn(W2[i]);
    }
    for (int i = tid; i < HID * NPAD; i += NTHREADS) {
        int k = i / NPAD, n = i - k * NPAD;
        hW3[k * W3ST + n] = __float2half_rn((n < OUTD) ? W3[k * OUTD + n] : 0.0f);
    }
    for (int i = tid; i < 7 * HID; i += NTHREADS) sW1[i] = W1[i];
    if (tid < HID) { sB1[tid] = b1[tid]; sB2[tid] = b2[tid]; }
    if (tid < NPAD) sB3[tid] = (tid < OUTD) ? b3[tid] : 0.0f;

    for (long tile = blockIdx.x; tile < ntiles; tile += gridDim.x) {
        const long base = tile * MROWS;
        const int nrows = (int)min((long)MROWS, (long)B - base);
        __syncthreads();

        // ---- stage inputs ----
        for (int i = tid; i < MROWS * XDIM; i += NTHREADS) {
            int r = i / XDIM, cc = i - r * XDIM;
            float v = (r < nrows) ? x[(base + r) * XDIM + cc] : 0.0f;
            if (cc < LOWERD) sLow[r * 4 + cc] = v;
            else             sIn[r * 8 + (cc - LOWERD)] = v;
        }
        for (int i = tid; i < MROWS * CDIM; i += NTHREADS) {
            int r = i >> 2, cc = i & 3;
            sIn[r * 8 + 3 + cc] = (r < nrows) ? c[(base + r) * CDIM + cc] : 0.0f;
        }
        __syncthreads();

        // ---- layer 1 (fp32) -> split fp16 A (h1 exact in hi+lo) ----
        for (int t = tid; t < MROWS * 64; t += NTHREADS) {
            int r = t >> 6, np = (t & 63) << 1;
            float a0 = sB1[np], a1 = sB1[np + 1];
            const float* inr = &sIn[r * 8];
            #pragma unroll
            for (int k = 0; k < 7; k++) {
                float iv = inr[k];
                a0 = fmaf(iv, sW1[k * HID + np], a0);
                a1 = fmaf(iv, sW1[k * HID + np + 1], a1);
            }
            a0 = fmaxf(a0, 0.0f); a1 = fmaxf(a1, 0.0f);
            __half h0 = __float2half_rn(a0), h1v = __float2half_rn(a1);
            __half l0 = __float2half_rn(a0 - __half2float(h0));
            __half l1 = __float2half_rn(a1 - __half2float(h1v));
            *(__half2*)&hAh[r * AST + np] = __halves2half2(h0, h1v);
            *(__half2*)&hAl[r * AST + np] = __halves2half2(l0, l1);
        }
        __syncthreads();

        // ---- GEMM2: 128x128x128, split-A, warp tile 16x64, k staggered ----
        float acc[8][4];
        {
            #pragma unroll
            for (int nt = 0; nt < 8; nt++)
                #pragma unroll
                for (int q = 0; q < 4; q++) acc[nt][q] = 0.0f;
            const int n0 = wn * 64;
            #pragma unroll
            for (int ki = 0; ki < 8; ki++) {
                const int kb = ((ki + warp) & 7) * 16;   // stagger L1 bursts per warp
                uint32_t ah[4], al[4], bb[4][4];
                uint32_t aoff = (uint32_t)(((m0 + lr) * AST + kb + lc) * 2);
                ldsm_x4(sb + OFF_AH + aoff, ah[0], ah[1], ah[2], ah[3]);
                ldsm_x4(sb + OFF_AL + aoff, al[0], al[1], al[2], al[3]);
                #pragma unroll
                for (int np = 0; np < 4; np++) {
                    uint32_t boff = (uint32_t)(((kb + lr) * W2ST + n0 + np * 16 + lc) * 2);
                    ldsm_x4t(sb + OFF_W2 + boff, bb[np][0], bb[np][1], bb[np][2], bb[np][3]);
                }
                #pragma unroll
                for (int np = 0; np < 4; np++)
                    #pragma unroll
                    for (int j = 0; j < 2; j++) {
                        float* cc4 = acc[np * 2 + j];
                        mma16816(cc4, ah, bb[np][2 * j], bb[np][2 * j + 1]);
                        mma16816(cc4, al, bb[np][2 * j], bb[np][2 * j + 1]);
                    }
            }
        }
        __syncthreads();

        // ---- h2 = relu(D + b2) -> plain fp16 A (hi only; GEMM3 unsplit) ----
        {
            const int n0 = wn * 64;
            #pragma unroll
            for (int nt = 0; nt < 8; nt++) {
                int col = n0 + nt * 8 + gcol;
                float bb0 = sB2[col], bb1 = sB2[col + 1];
                #pragma unroll
                for (int h = 0; h < 2; h++) {
                    int r = m0 + grow + h * 8;
                    float v0 = fmaxf(acc[nt][2 * h]     + bb0, 0.0f);
                    float v1 = fmaxf(acc[nt][2 * h + 1] + bb1, 0.0f);
                    *(__half2*)&hAh[r * AST + col] =
                        __halves2half2(__float2half_rn(v0), __float2half_rn(v1));
                }
            }
        }
        __syncthreads();

        // ---- GEMM3: 128x144x128, plain-A, warp tile 16x72, k staggered ----
        {
            float a3[9][4];
            #pragma unroll
            for (int nt = 0; nt < 9; nt++)
                #pragma unroll
                for (int q = 0; q < 4; q++) a3[nt][q] = 0.0f;
            const int n0 = wn * 72;
            #pragma unroll
            for (int ki = 0; ki < 8; ki++) {
                const int kb = ((ki + warp) & 7) * 16;
                uint32_t ah[4], bb[4][4], be[2];
                uint32_t aoff = (uint32_t)(((m0 + lr) * AST + kb + lc) * 2);
                ldsm_x4(sb + OFF_AH + aoff, ah[0], ah[1], ah[2], ah[3]);
                #pragma unroll
                for (int np = 0; np < 4; np++) {
                    uint32_t boff = (uint32_t)(((kb + lr) * W3ST + n0 + np * 16 + lc) * 2);
                    ldsm_x4t(sb + OFF_W3 + boff, bb[np][0], bb[np][1], bb[np][2], bb[np][3]);
                }
                {
                    uint32_t boff = (uint32_t)(((kb + lr) * W3ST + n0 + 64) * 2);
                    ldsm_x2t(sb + OFF_W3 + boff, be[0], be[1]);
                }
                #pragma unroll
                for (int np = 0; np < 4; np++)
                    #pragma unroll
                    for (int j = 0; j < 2; j++)
                        mma16816(a3[np * 2 + j], ah, bb[np][2 * j], bb[np][2 * j + 1]);
                mma16816(a3[8], ah, be[0], be[1]);
            }
            #pragma unroll
            for (int nt = 0; nt < 9; nt++) {
                int col = n0 + nt * 8 + gcol;
                float bb0 = sB3[col], bb1 = sB3[col + 1];
                #pragma unroll
                for (int h = 0; h < 2; h++) {
                    int r = m0 + grow + h * 8;
                    sP[r * PST + col]     = a3[nt][2 * h]     + bb0;
                    sP[r * PST + col + 1] = a3[nt][2 * h + 1] + bb1;
                }
            }
        }
        __syncthreads();

        // ---- spline epilogue (FFMA-pipe transcendentals) ----
        if (tid < MROWS * LOWERD) {
            const int item = tid;
            const int r = item / 3;
            const int d = item - r * 3;
            const float* p = &sP[r * PST + d * SPLD];
            const float xv = sLow[r * 4 + d];
            const bool oob = (xv <= -BOUNDV) || (xv >= BOUNDV);
            const float xm = oob ? -BOUNDV : xv;

            float mW = -1e30f;
            #pragma unroll
            for (int i = 0; i < KNOTS; i++) mW = fmaxf(mW, p[i]);
            float ew[KNOTS], S = 0.0f;
            #pragma unroll
            for (int i = 0; i < KNOTS; i++) { ew[i] = fexp(p[i] - mW); S += ew[i]; }
            const float invS = __fdividef(2.0f * BOUNDV, S);

            int idx = 0; float cumex = 0.0f, wsel = ew[0];
            bool found = false; float cum = 0.0f;
            #pragma unroll
            for (int i = 0; i < KNOTS; i++) {
                float cn = cum + ew[i];
                bool take = (!found) && (xm < fmaf(cn, invS, -BOUNDV));
                if (take) { found = true; idx = i; cumex = cum; wsel = ew[i]; }
                cum = cn;
            }
            if (!found) { idx = KNOTS - 1; cumex = cum - ew[KNOTS - 1]; wsel = ew[KNOTS - 1]; }

            const float xk_b = fmaf(cumex, invS, -BOUNDV);
            const float wk   = wsel * invS;

            float mH = -1e30f;
            #pragma unroll
            for (int i = 0; i < KNOTS; i++) mH = fmaxf(mH, p[KNOTS + i]);
            float SH = 0.0f, cumh = 0.0f, hsel = 0.0f;
            #pragma unroll
            for (int i = 0; i < KNOTS; i++) {
                float e = fexp(p[KNOTS + i] - mH);
                SH += e;
                if (i < idx)  cumh += e;
                if (i == idx) hsel = e;
            }
            const float invSH = __fdividef(2.0f * BOUNDV, SH);
            const float yk_b = fmaf(cumh, invSH, -BOUNDV);
            const float hk   = hsel * invSH;

            float d0 = 1.0f, d1 = 1.0f;
            if (idx > 0)         d0 = softplus_f(p[2 * KNOTS + idx - 1]);
            if (idx < KNOTS - 1) d1 = softplus_f(p[2 * KNOTS + idx]);

            const float rwk = __fdividef(1.0f, wk);
            const float sk = hk * rwk;
            float relx = fminf(fmaxf((xm - xk_b) * rwk, 0.0f), 1.0f);
            const float omr = 1.0f - relx;
            const float r1 = relx * omr;
            const float den = sk + (d1 + d0 - 2.0f * sk) * r1;
            const float rden = __fdividef(1.0f, den);
            const float num = hk * (sk * relx * relx + d0 * r1);
            float y = yk_b + num * rden;
            const float arg = d1 * relx * relx + 2.0f * sk * r1 + d0 * omr * omr;
            float ld = flog(sk * sk * arg * rden * rden);
            if (oob) { y = xv; ld = 0.0f; }

            sLd[r * 4 + d] = ld;
            if (r < nrows) {
                out[(base + r) * XDIM + d] = y;
                out[(base + r) * XDIM + LOWERD + d] = sIn[r * 8 + d];
            }
        }
        __syncthreads();
        if (tid < MROWS && tid < nrows)
            out[(long)B * XDIM + base + tid] =
                sLd[tid * 4] + sLd[tid * 4 + 1] + sLd[tid * 4 + 2];
    }
}

extern "C" void kernel_launch(void* const* d_in, const int* in_sizes, int n_in,
                              void* d_out, int out_size)
{
    const float* x  = (const float*)d_in[0];
    const float* c  = (const float*)d_in[1];
    const float* W1 = (const float*)d_in[2];
    const float* b1 = (const float*)d_in[3];
    const float* W2 = (const float*)d_in[4];
    const float* b2 = (const float*)d_in[5];
    const float* W3 = (const float*)d_in[6];
    const float* b3 = (const float*)d_in[7];
    (void)n_in; (void)out_size;

    const int B = in_sizes[0] / XDIM;
    const int ntiles = (B + MROWS - 1) / MROWS;
    float* out = (float*)d_out;

    int sms = 148;
    cudaDeviceGetAttribute(&sms, cudaDevAttrMultiProcessorCount, 0);
    int grid = sms < ntiles ? sms : ntiles;

    cudaFuncSetAttribute(nsc_hmma_kernel, cudaFuncAttributeMaxDynamicSharedMemorySize,
                         SMEM_BYTES);
    nsc_hmma_kernel<<<grid, NTHREADS, SMEM_BYTES>>>(x, c, W1, b1, W2, b2, W3, b3,
                                                    out, B, ntiles);
}